// round 16
// baseline (speedup 1.0000x reference)
#include <cuda_runtime.h>

// DenseRadiusGraph: B=16 graphs, N=2048 nodes, D=3, cutoff=10, K=32.
// Output (float32, concat, M = B*N*K = 1048576):
//   [0,M) row ids, [M,2M) col ids, [2M,3M) weights, [3M,4M) valid flags.
//
// R16: (a) bin pipeline made chip-wide (pack+hist / prefix+reset / scatter,
// global atomics) instead of 16 resident blocks; (b) scan's 64-bit bitonic
// sort replaced by rank-by-counting over the compacted keys (unique keys ->
// exact total order, ~45 inst vs ~80).

#define BGRAPHS 16
#define NNODES  2048
#define KNBR    32
#define NTOT    (BGRAPHS * NNODES)
#define NCELL   1000                  // 10x10x10 cells of width 10 = cutoff
#define TPB     256
#define WPB     (TPB / 32)            // 8 warps (nodes) per block
#define BLKS_G  (NNODES / WPB)        // 256 blocks per graph -> grid 4096

typedef unsigned long long ull;
#define KEY_INF 0xFFFFFFFFFFFFFFFFull
#define FULLM   0xFFFFFFFFu

// device scratch (static globals -- no allocation; zero-initialized)
__device__ float4 g_packed[NTOT];              // x,y,z, 0.5*|p|^2 (orig order)
__device__ float4 g_sorted[NTOT];              // cell-sorted copy
__device__ int    g_sidx[NTOT];                // original index of sorted entry
__device__ int    g_cellcnt[BGRAPHS][NCELL];   // histogram (reset each run)
__device__ int    g_cellcur[BGRAPHS][NCELL];   // scatter cursors
__device__ int    g_cellstart[BGRAPHS][NCELL + 1];

__device__ __forceinline__ int3 cell_of(float x, float y, float z)
{
    return make_int3(min(9, (int)(x * 0.1f)),
                     min(9, (int)(y * 0.1f)),
                     min(9, (int)(z * 0.1f)));
}

__device__ __forceinline__ int cell_id(float x, float y, float z)
{
    const int3 cc = cell_of(x, y, z);
    return (cc.x * 10 + cc.y) * 10 + cc.z;
}

// chip-wide: pack positions + global histogram
__global__ __launch_bounds__(TPB) void pack_hist_kernel(const float* __restrict__ pos)
{
    const int t = blockIdx.x * blockDim.x + threadIdx.x;
    if (t >= NTOT) return;
    const int b = t >> 11;                    // t / NNODES
    const float x = pos[3 * t + 0];
    const float y = pos[3 * t + 1];
    const float z = pos[3 * t + 2];
    g_packed[t] = make_float4(x, y, z, 0.5f * (x * x + y * y + z * z));
    atomicAdd(&g_cellcnt[b][cell_id(x, y, z)], 1);
}

// one warp per graph: prefix over 1000 counts; writes starts+cursors and
// RESETS g_cellcnt to zero (keeps graph replay deterministic, no extra kernel)
__global__ __launch_bounds__(32) void prefix_kernel()
{
    const int b = blockIdx.x;
    const int lane = threadIdx.x;

    int v[32];
    int own = 0;
    #pragma unroll
    for (int k = 0; k < 32; k++) {
        const int c = 32 * lane + k;
        v[k] = (c < NCELL) ? g_cellcnt[b][c] : 0;
        own += v[k];
    }
    int inc = own;
    #pragma unroll
    for (int off = 1; off < 32; off <<= 1) {
        const int u = __shfl_up_sync(FULLM, inc, off);
        if (lane >= off) inc += u;
    }
    int acc = inc - own;                      // exclusive base
    #pragma unroll
    for (int k = 0; k < 32; k++) {
        const int c = 32 * lane + k;
        if (c < NCELL) {
            g_cellstart[b][c] = acc;
            g_cellcur[b][c]   = acc;
            g_cellcnt[b][c]   = 0;            // reset for next replay
        }
        acc += v[k];
    }
    if (lane == 31) g_cellstart[b][NCELL] = NNODES;
}

// chip-wide scatter into cell-sorted order
__global__ __launch_bounds__(TPB) void scatter_kernel()
{
    const int t = blockIdx.x * blockDim.x + threadIdx.x;
    if (t >= NTOT) return;
    const int b = t >> 11;
    const int n = t & (NNODES - 1);
    const float4 p4 = g_packed[t];
    const int c = cell_id(p4.x, p4.y, p4.z);
    const int p = atomicAdd(&g_cellcur[b][c], 1);
    g_sorted[(size_t)b * NNODES + p] = p4;
    g_sidx[(size_t)b * NNODES + p]  = n;
}

__global__ __launch_bounds__(TPB) void scan_kernel(float* __restrict__ out)
{
    __shared__ ull sbuf[WPB][64];
    __shared__ ull rbuf[WPB][64];
    __shared__ int smap[WPB][128];

    const int b    = blockIdx.x / BLKS_G;
    const int blk  = blockIdx.x % BLKS_G;
    const int w    = threadIdx.x >> 5;
    const int lane = threadIdx.x & 31;

    const float4* __restrict__ gs = g_sorted + (size_t)b * NNODES;
    const int*    __restrict__ gi = g_sidx   + (size_t)b * NNODES;

    const int sp = blk * WPB + w;             // sorted position (warp's node)
    const float4 me = gs[sp];                 // warp-uniform broadcast
    const int i = gi[sp];                     // original node index
    const float mew = 2.0f * me.w;            // exact |me|^2
    const int3 cc = cell_of(me.x, me.y, me.z);

    // lane s < 9 owns (dx,dy) column s: contiguous range in sorted array
    int lo = 0, len = 0;
    if (lane < 9) {
        const int cxn = cc.x + (lane / 3) - 1;
        const int cyn = cc.y + (lane % 3) - 1;
        if (cxn >= 0 && cxn < 10 && cyn >= 0 && cyn < 10) {
            const int basec = (cxn * 10 + cyn) * 10;
            const int zlo = max(cc.z - 1, 0);
            const int zhi = min(cc.z + 1, 9);
            lo  = g_cellstart[b][basec + zlo];
            len = g_cellstart[b][basec + zhi + 1] - lo;
        }
    }

    // inclusive shfl scan of len over lanes 0..8
    int inc = len;
    #pragma unroll
    for (int off = 1; off < 16; off <<= 1) {
        const int u = __shfl_up_sync(FULLM, inc, off);
        if (lane >= off) inc += u;
    }
    const int T = __shfl_sync(FULLM, inc, 8);     // total candidates (<=128)

    // scatter-map: lane s writes its contiguous index range into smap
    if (lane < 9) {
        int dst = inc - len;
        for (int k = 0; k < len && dst < 128; k++, dst++)
            smap[w][dst] = lo + k;
    }
    sbuf[w][lane]      = KEY_INF;
    sbuf[w][lane + 32] = KEY_INF;
    rbuf[w][lane]      = KEY_INF;
    rbuf[w][lane + 32] = KEY_INF;
    __syncwarp();

    // dynamic candidate rounds: avg ~2.1 (T ~ 55), capped at 4
    const int rounds = min((T + 31) >> 5, 4);
    const unsigned lt = (1u << lane) - 1u;
    int cnt = 0;
    for (int r = 0; r < rounds; r++) {
        const int c = lane + (r << 5);
        const int idc = (c < T) ? smap[w][c] : sp;    // dummy -> own node
        const float4 pj = gs[idc];
        const int j = gi[idc];
        // exact reference formulation, bit-identical to prior rounds:
        const float pw  = 2.0f * pj.w;
        const float dot = me.x * pj.x + me.y * pj.y + me.z * pj.z;
        const float d2  = (mew + pw) - 2.0f * dot;
        const float dist = sqrtf(fmaxf(d2, 0.0f));
        // dist>=0 -> bit order == float order; low bits = j -> stable
        // lower-index tie-break (matches lax.top_k).
        const ull key = (j != i && dist <= 10.0f)
            ? (((ull)__float_as_uint(dist) << 32) | (unsigned int)j)
            : KEY_INF;
        const unsigned bal = __ballot_sync(FULLM, key != KEY_INF);
        if (key != KEY_INF) {
            const int rank = cnt + __popc(bal & lt);
            if (rank < 64) sbuf[w][rank] = key;
        }
        cnt += __popc(bal);
    }
    __syncwarp();

    // rank-by-counting (keys unique -> exact total order, no ties)
    const int cb = min(cnt, 64);
    if (cnt <= 32) {                          // warp-uniform; ~always
        const ull mine = sbuf[w][lane];
        int r = 0;
        for (int c = 0; c < cb; c++)
            r += (sbuf[w][c] < mine) ? 1 : 0; // LDS broadcast per iter
        if (mine != KEY_INF) rbuf[w][r] = mine;
    } else {                                  // rare exact path
        const ull m0 = sbuf[w][lane];
        const ull m1 = sbuf[w][lane + 32];
        int r0 = 0, r1 = 0;
        for (int c = 0; c < cb; c++) {
            const ull kc = sbuf[w][c];
            r0 += (kc < m0) ? 1 : 0;
            r1 += (kc < m1) ? 1 : 0;
        }
        if (m0 != KEY_INF) rbuf[w][r0] = m0;
        if (m1 != KEY_INF && r1 < 64) rbuf[w][r1] = m1;
    }
    __syncwarp();
    const ull key = rbuf[w][lane];            // k-th nearest for lane k

    // epilogue: lane k writes edge k of node i (all stores coalesced)
    const size_t M = (size_t)BGRAPHS * NNODES * KNBR;
    const size_t gidx = (size_t)b * NNODES + i;
    float rowv = 0.0f, colv = 0.0f, wv = 0.0f, vv = 0.0f;
    if (key != KEY_INF) {
        const int j = (int)(key & 0xffffffffu);
        const float4 p = g_packed[(size_t)b * NNODES + j];
        const float dx = me.x - p.x;
        const float dy = me.y - p.y;
        const float dz = me.z - p.z;
        wv   = sqrtf(dx * dx + dy * dy + dz * dz);   // recomputed, as reference
        rowv = (float)gidx;
        colv = (float)(b * NNODES + j);
        vv   = 1.0f;
    }
    out[gidx * KNBR + lane]         = rowv;
    out[M + gidx * KNBR + lane]     = colv;
    out[2 * M + gidx * KNBR + lane] = wv;
    out[3 * M + gidx * KNBR + lane] = vv;
}

extern "C" void kernel_launch(void* const* d_in, const int* in_sizes, int n_in,
                              void* d_out, int out_size)
{
    const float* pos = (const float*)d_in[0];
    float* out = (float*)d_out;

    pack_hist_kernel<<<NTOT / TPB, TPB>>>(pos);   // 128 blocks, chip-wide
    prefix_kernel<<<BGRAPHS, 32>>>();             // tiny
    scatter_kernel<<<NTOT / TPB, TPB>>>();        // 128 blocks, chip-wide
    scan_kernel<<<BGRAPHS * BLKS_G, TPB>>>(out);  // 4096 blocks
}